// round 12
// baseline (speedup 1.0000x reference)
#include <cuda_runtime.h>

// Problem constants (fixed by setup_inputs)
#define BB    16
#define CIN   64
#define COUT  64
#define HH    224
#define WW    224
#define PHH   32
#define PWW   32
#define PLANE   (HH * WW)

// Conv: split-cin x4. CTA = (b, 8-co tile, 8-row tile, cin-quarter) -> 2048 CTAs
#define CIN_T 16
#define NSPLIT 4
#define CO_T  8
#define OH_T  8
#define CONV_BLOCKS (BB * (COUT / CO_T) * (PHH / OH_T) * NSPLIT)  // 2048
#define NTHREADS 256

#define SIN_STRIDE_R 36
#define SIN_STRIDE_C (10 * SIN_STRIDE_R)   // 360

#define PATCH_ELEMS (BB * COUT * PHH * PWW)          // 1,048,576

// Partial sums: one 4 MB slab per cin-quarter (16 MB total, static device mem)
__device__ float g_part[NSPLIT * PATCH_ELEMS];

__device__ __forceinline__ unsigned long long pack2(float v) {
    unsigned long long r;
    asm("mov.b64 %0, {%1, %1};" : "=l"(r) : "f"(v));
    return r;
}
__device__ __forceinline__ void ffma2(unsigned long long& acc,
                                      unsigned long long w,
                                      unsigned long long v) {
    asm("fma.rn.f32x2 %0, %1, %2, %0;" : "+l"(acc) : "l"(w), "l"(v));
}

__global__ __launch_bounds__(NTHREADS, 6)
void inc_conv_partial_kernel(const float* __restrict__ in,      // (B,Cin,H,W)
                             const float* __restrict__ wgt,     // (Cout,Cin,3,3)
                             const int*   __restrict__ locs)    // (B,2) [y,x]
{
    __shared__ float s_in[CIN_T * SIN_STRIDE_C];            // 23040 B
    __shared__ __align__(16) float s_w[CIN_T * 9 * CO_T];   //  4608 B

    const int tid = threadIdx.x;
    const int kq      = blockIdx.x & 3;                 // cin quarter
    const int ohtile  = (blockIdx.x >> 2) & 3;
    const int cotile  = (blockIdx.x >> 4) & 7;
    const int b       = blockIdx.x >> 7;

    const int ci0 = kq * CIN_T;
    const int co0 = cotile * CO_T;
    const int oh0 = ohtile * OH_T;

    const int y = locs[2 * b];
    const int x = locs[2 * b + 1];

    const int oh_l = tid >> 5;                  // 0..7
    const int ow   = tid & 31;                  // 0..31

    unsigned long long acc[4];                  // 8 couts as 4 f32x2
    #pragma unroll
    for (int c = 0; c < 4; ++c) acc[c] = 0ULL;

    const int gr0 = y + oh0 - 1;
    const int gc0 = x - 1;

    // load this CTA's single 16-cin chunk
    for (int t = tid; t < CIN_T * 10 * 34; t += NTHREADS) {
        const int ci = t / (10 * 34);
        const int r  = (t / 34) % 10;
        const int c  = t % 34;
        const int gr = gr0 + r;
        const int gc = gc0 + c;
        float v = 0.0f;
        if (gr >= 0 && gc >= 0)   // high side provably in-bounds
            v = in[((size_t)(b * CIN + ci0 + ci) * HH + gr) * WW + gc];
        s_in[ci * SIN_STRIDE_C + r * SIN_STRIDE_R + c] = v;
    }
    for (int t = tid; t < CO_T * CIN_T * 9; t += NTHREADS) {
        const int co = t / (CIN_T * 9);
        const int r2 = t % (CIN_T * 9);
        const int ci = r2 / 9;
        const int k  = r2 % 9;
        s_w[(ci * 9 + k) * CO_T + co] =
            wgt[((co0 + co) * CIN + ci0 + ci) * 9 + k];
    }
    __syncthreads();

    #pragma unroll 4
    for (int ci = 0; ci < CIN_T; ++ci) {
        const float* ibase = &s_in[ci * SIN_STRIDE_C + oh_l * SIN_STRIDE_R + ow];
        #pragma unroll
        for (int kh = 0; kh < 3; ++kh) {
            const float i0 = ibase[kh * SIN_STRIDE_R + 0];
            const float i1 = ibase[kh * SIN_STRIDE_R + 1];
            const float i2 = ibase[kh * SIN_STRIDE_R + 2];
            #pragma unroll
            for (int kw = 0; kw < 3; ++kw) {
                const float ivs = (kw == 0) ? i0 : ((kw == 1) ? i1 : i2);
                const unsigned long long vv = pack2(ivs);
                const ulonglong2* wp =
                    (const ulonglong2*)&s_w[(ci * 9 + kh * 3 + kw) * CO_T];
                const ulonglong2 wa = wp[0], wb = wp[1];
                ffma2(acc[0], wa.x, vv);  ffma2(acc[1], wa.y, vv);
                ffma2(acc[2], wb.x, vv);  ffma2(acc[3], wb.y, vv);
            }
        }
    }

    // store partials: g_part[kq][b][co][row][col]
    const int row = oh0 + oh_l;
    float* base = &g_part[kq * PATCH_ELEMS];
    #pragma unroll
    for (int j = 0; j < 4; ++j) {
        float lo, hi;
        asm("mov.b64 {%0, %1}, %2;" : "=f"(lo), "=f"(hi) : "l"(acc[j]));
        const int coA = co0 + 2 * j;
        base[(((b * COUT + coA) * PHH) + row) * PWW + ow]     = lo;
        base[(((b * COUT + coA + 1) * PHH) + row) * PWW + ow] = hi;
    }
}

// Sum the 4 partials + bias and splice into dst over the stale copy.
__global__ __launch_bounds__(NTHREADS)
void patch_fixup_kernel(const float* __restrict__ bias,
                        const int* __restrict__ locs,
                        float* __restrict__ dst)
{
    const int t  = blockIdx.x * NTHREADS + threadIdx.x;   // 262144 threads
    const int c4 = t & 7;              // float4 within a row
    const int r  = (t >> 3) & 31;
    const int co = (t >> 8) & 63;
    const int b  = t >> 14;

    const int idx = (((b * COUT + co) * PHH) + r) * PWW + c4 * 4;

    float4 s = *(const float4*)&g_part[idx];
    #pragma unroll
    for (int q = 1; q < NSPLIT; ++q) {
        const float4 p = *(const float4*)&g_part[q * PATCH_ELEMS + idx];
        s.x += p.x; s.y += p.y; s.z += p.z; s.w += p.w;
    }
    const float bv = __ldg(&bias[co]);
    s.x += bv; s.y += bv; s.z += bv; s.w += bv;

    const int py = __ldg(&locs[2 * b]);
    const int px = __ldg(&locs[2 * b + 1]);

    float* d = &dst[(size_t)(b * COUT + co) * PLANE +
                    (size_t)(py + r) * WW + px + 4 * c4];
    d[0] = s.x; d[1] = s.y; d[2] = s.z; d[3] = s.w;
}

// Side stream + events created at static init (no device-memory APIs used).
static cudaStream_t g_side = nullptr;
static cudaEvent_t  g_fork = nullptr, g_join = nullptr;
namespace {
struct StreamInit {
    StreamInit() {
        cudaStreamCreateWithFlags(&g_side, cudaStreamNonBlocking);
        cudaEventCreateWithFlags(&g_fork, cudaEventDisableTiming);
        cudaEventCreateWithFlags(&g_join, cudaEventDisableTiming);
    }
};
static StreamInit g_stream_init;
}

extern "C" void kernel_launch(void* const* d_in, const int* in_sizes, int n_in,
                              void* d_out, int out_size) {
    const float* in_tensor  = (const float*)d_in[0];
    const float* weights    = (const float*)d_in[1];
    const float* biases     = (const float*)d_in[2];
    const float* out_stale  = (const float*)d_in[3];
    const int*   locs       = (const int*)d_in[4];
    float*       out        = (float*)d_out;

    // Fork: conv partials on side stream (any overlap with the copy is upside).
    cudaEventRecord(g_fork, 0);
    cudaStreamWaitEvent(g_side, g_fork, 0);
    inc_conv_partial_kernel<<<CONV_BLOCKS, NTHREADS, 0, g_side>>>(
        in_tensor, weights, locs);
    cudaEventRecord(g_join, g_side);

    // Main stream: vendor bulk copy of the stale output (patches overwritten later).
    cudaMemcpyAsync(out, out_stale, (size_t)in_sizes[3] * sizeof(float),
                    cudaMemcpyDeviceToDevice, 0);

    // Join, then splice summed partials (+bias) over the stale patch regions.
    cudaStreamWaitEvent(0, g_join, 0);
    patch_fixup_kernel<<<(PATCH_ELEMS / 4) / NTHREADS, NTHREADS>>>(
        biases, locs, out);
}

// round 13
// speedup vs baseline: 1.1603x; 1.1603x over previous
#include <cuda_runtime.h>

// Problem constants (fixed by setup_inputs)
#define BB    16
#define CIN   64
#define COUT  64
#define HH    224
#define WW    224
#define PHH   32
#define PWW   32
#define PLANE   (HH * WW)
#define TOTAL4  (BB * COUT * PLANE / 4)    // 12,845,056 float4s

// Conv: split-cin x2. CTA = (b, 8-co, 8-row, cin-half) -> 1024 CTAs
#define CIN_T 16
#define NSPLIT 2
#define CIN_PER (CIN / NSPLIT)             // 32
#define CO_T  8
#define OH_T  8
#define CONV_BLOCKS (BB * (COUT / CO_T) * (PHH / OH_T) * NSPLIT)  // 1024
#define COPY_BLOCKS 2048
#define NTHREADS 256
// each copy CTA owns a contiguous chunk of float4s
#define CHUNK4 ((TOTAL4 + COPY_BLOCKS - 1) / COPY_BLOCKS)   // 6272

#define SIN_STRIDE_R 36
#define SIN_STRIDE_C (10 * SIN_STRIDE_R)   // 360

#define PATCH_ELEMS (BB * COUT * PHH * PWW)   // 1,048,576

// Partial sums: one 4 MB slab per cin-half (8 MB static device mem)
__device__ float g_part[NSPLIT * PATCH_ELEMS];

__device__ __forceinline__ unsigned long long pack2(float v) {
    unsigned long long r;
    asm("mov.b64 %0, {%1, %1};" : "=l"(r) : "f"(v));
    return r;
}
__device__ __forceinline__ void ffma2(unsigned long long& acc,
                                      unsigned long long w,
                                      unsigned long long v) {
    asm("fma.rn.f32x2 %0, %1, %2, %0;" : "+l"(acc) : "l"(w), "l"(v));
}

__global__ __launch_bounds__(NTHREADS, 6)
void inc_conv_fused_kernel(const float* __restrict__ in,      // (B,Cin,H,W)
                           const float* __restrict__ wgt,     // (Cout,Cin,3,3)
                           const float* __restrict__ src_out, // (B,Cout,H,W)
                           const int*   __restrict__ locs,    // (B,2) [y,x]
                           float*       __restrict__ dst)     // (B,Cout,H,W)
{
    const int tid = threadIdx.x;

    if (blockIdx.x >= CONV_BLOCKS) {
        // ---------- COPY ROLE: flat, vendor-style, whole buffer ----------
        const int id = blockIdx.x - CONV_BLOCKS;
        const float4* __restrict__ s4 = (const float4*)src_out;
        float4*       __restrict__ d4 = (float4*)dst;

        const int lo = id * CHUNK4;
        int hi = lo + CHUNK4;
        if (hi > TOTAL4) hi = TOTAL4;

        int i = lo + tid;
        // 4-way unrolled contiguous copy, plain ld/st
        for (; i + 3 * NTHREADS < hi; i += 4 * NTHREADS) {
            const float4 v0 = s4[i];
            const float4 v1 = s4[i + NTHREADS];
            const float4 v2 = s4[i + 2 * NTHREADS];
            const float4 v3 = s4[i + 3 * NTHREADS];
            d4[i]                = v0;
            d4[i + NTHREADS]     = v1;
            d4[i + 2 * NTHREADS] = v2;
            d4[i + 3 * NTHREADS] = v3;
        }
        for (; i < hi; i += NTHREADS) d4[i] = s4[i];
        return;
    }

    // ---------- CONV ROLE: partials to scratch (split-cin x2) ----------
    __shared__ float s_in[CIN_T * SIN_STRIDE_C];            // 23040 B
    __shared__ __align__(16) float s_w[CIN_T * 9 * CO_T];   //  4608 B

    const int kq     = blockIdx.x & 1;                 // cin half
    const int ohtile = (blockIdx.x >> 1) & 3;
    const int cotile = (blockIdx.x >> 3) & 7;
    const int b      = blockIdx.x >> 6;

    const int cbase = kq * CIN_PER;
    const int co0   = cotile * CO_T;
    const int oh0   = ohtile * OH_T;

    const int y = locs[2 * b];
    const int x = locs[2 * b + 1];

    const int oh_l = tid >> 5;
    const int ow   = tid & 31;

    unsigned long long acc[4];                  // 8 couts as 4 f32x2
    #pragma unroll
    for (int c = 0; c < 4; ++c) acc[c] = 0ULL;

    const int gr0 = y + oh0 - 1;
    const int gc0 = x - 1;

    for (int cc = 0; cc < CIN_PER; cc += CIN_T) {
        const int ci0 = cbase + cc;
        for (int t = tid; t < CIN_T * 10 * 34; t += NTHREADS) {
            const int ci = t / (10 * 34);
            const int r  = (t / 34) % 10;
            const int c  = t % 34;
            const int gr = gr0 + r;
            const int gc = gc0 + c;
            float v = 0.0f;
            if (gr >= 0 && gc >= 0)   // high side provably in-bounds
                v = in[((size_t)(b * CIN + ci0 + ci) * HH + gr) * WW + gc];
            s_in[ci * SIN_STRIDE_C + r * SIN_STRIDE_R + c] = v;
        }
        for (int t = tid; t < CO_T * CIN_T * 9; t += NTHREADS) {
            const int co = t / (CIN_T * 9);
            const int r2 = t % (CIN_T * 9);
            const int ci = r2 / 9;
            const int k  = r2 % 9;
            s_w[(ci * 9 + k) * CO_T + co] =
                wgt[((co0 + co) * CIN + ci0 + ci) * 9 + k];
        }
        __syncthreads();

        #pragma unroll 4
        for (int ci = 0; ci < CIN_T; ++ci) {
            const float* ibase = &s_in[ci * SIN_STRIDE_C + oh_l * SIN_STRIDE_R + ow];
            #pragma unroll
            for (int kh = 0; kh < 3; ++kh) {
                const float i0 = ibase[kh * SIN_STRIDE_R + 0];
                const float i1 = ibase[kh * SIN_STRIDE_R + 1];
                const float i2 = ibase[kh * SIN_STRIDE_R + 2];
                #pragma unroll
                for (int kw = 0; kw < 3; ++kw) {
                    const float ivs = (kw == 0) ? i0 : ((kw == 1) ? i1 : i2);
                    const unsigned long long vv = pack2(ivs);
                    const ulonglong2* wp =
                        (const ulonglong2*)&s_w[(ci * 9 + kh * 3 + kw) * CO_T];
                    const ulonglong2 wa = wp[0], wb = wp[1];
                    ffma2(acc[0], wa.x, vv);  ffma2(acc[1], wa.y, vv);
                    ffma2(acc[2], wb.x, vv);  ffma2(acc[3], wb.y, vv);
                }
            }
        }
        __syncthreads();
    }

    // store partials: g_part[kq][b][co][row][col]
    const int row = oh0 + oh_l;
    float* base = &g_part[kq * PATCH_ELEMS];
    #pragma unroll
    for (int j = 0; j < 4; ++j) {
        float lo, hi;
        asm("mov.b64 {%0, %1}, %2;" : "=f"(lo), "=f"(hi) : "l"(acc[j]));
        const int coA = co0 + 2 * j;
        base[(((b * COUT + coA) * PHH) + row) * PWW + ow]     = lo;
        base[(((b * COUT + coA + 1) * PHH) + row) * PWW + ow] = hi;
    }
}

// Sum the partials + bias and splice over the stale copy in dst.
__global__ __launch_bounds__(NTHREADS)
void patch_fixup_kernel(const float* __restrict__ bias,
                        const int* __restrict__ locs,
                        float* __restrict__ dst)
{
    const int t  = blockIdx.x * NTHREADS + threadIdx.x;   // 262144 threads
    const int c4 = t & 7;
    const int r  = (t >> 3) & 31;
    const int co = (t >> 8) & 63;
    const int b  = t >> 14;

    const int idx = (((b * COUT + co) * PHH) + r) * PWW + c4 * 4;

    float4 s = *(const float4*)&g_part[idx];
    #pragma unroll
    for (int q = 1; q < NSPLIT; ++q) {
        const float4 p = *(const float4*)&g_part[q * PATCH_ELEMS + idx];
        s.x += p.x; s.y += p.y; s.z += p.z; s.w += p.w;
    }
    const float bv = __ldg(&bias[co]);
    s.x += bv; s.y += bv; s.z += bv; s.w += bv;

    const int py = __ldg(&locs[2 * b]);
    const int px = __ldg(&locs[2 * b + 1]);

    float* d = &dst[(size_t)(b * COUT + co) * PLANE +
                    (size_t)(py + r) * WW + px + 4 * c4];
    d[0] = s.x; d[1] = s.y; d[2] = s.z; d[3] = s.w;
}

extern "C" void kernel_launch(void* const* d_in, const int* in_sizes, int n_in,
                              void* d_out, int out_size) {
    const float* in_tensor  = (const float*)d_in[0];
    const float* weights    = (const float*)d_in[1];
    const float* biases     = (const float*)d_in[2];
    const float* out_stale  = (const float*)d_in[3];
    const int*   locs       = (const int*)d_in[4];
    float*       out        = (float*)d_out;

    // Fused: flat full-buffer copy + conv partials to scratch (no dst hazard).
    inc_conv_fused_kernel<<<CONV_BLOCKS + COPY_BLOCKS, NTHREADS>>>(
        in_tensor, weights, out_stale, locs, out);

    // Then splice summed partials (+bias) over the stale patch regions.
    patch_fixup_kernel<<<(PATCH_ELEMS / 4) / NTHREADS, NTHREADS>>>(
        biases, locs, out);
}